// round 6
// baseline (speedup 1.0000x reference)
#include <cuda_runtime.h>
#include <math.h>

// Problem constants (fixed shapes from reference)
#define TTOK 8192
#define DDIM 2048
#define HDIM 8192
#define NEXP 8

// ---------------------------------------------------------------------------
// Scratch: __device__ globals (no cudaMalloc allowed anywhere)
// ---------------------------------------------------------------------------
__device__ int   g_is64;                 // expert_idxs dtype flag (1 = int64)
__device__ int   g_cnt[NEXP];
__device__ int   g_tok[NEXP * TTOK];
__device__ float g_gate[NEXP * TTOK];
__device__ float g_hbuf[(size_t)TTOK * (size_t)HDIM];  // 268 MB intermediate

// ---------------------------------------------------------------------------
// Packed f32x2 helpers (Blackwell fma.rn.f32x2 -> SASS FFMA2, 2x FFMA rate)
// ---------------------------------------------------------------------------
__device__ __forceinline__ unsigned long long pack2(float lo, float hi) {
    unsigned long long r;
    asm("mov.b64 %0, {%1, %2};" : "=l"(r) : "f"(lo), "f"(hi));
    return r;
}
__device__ __forceinline__ void ffma2(unsigned long long& d,
                                      unsigned long long a,
                                      unsigned long long b) {
    asm("fma.rn.f32x2 %0, %1, %2, %0;" : "+l"(d) : "l"(a), "l"(b));
}
__device__ __forceinline__ void unpack2(unsigned long long v, float& lo, float& hi) {
    asm("mov.b64 {%0, %1}, %2;" : "=f"(lo), "=f"(hi) : "l"(v));
}

// JAX default gelu: approximate=True (tanh form)
__device__ __forceinline__ float gelu_tanh(float v) {
    const float c = 0.7978845608028654f;  // sqrt(2/pi)
    float u = c * (v + 0.044715f * v * v * v);
    return 0.5f * v * (1.0f + tanhf(u));
}

// ---------------------------------------------------------------------------
// Dtype detection for expert_idxs: scan first 8192 int32 pairs. int64 ids in
// [0,8) have all-zero high words; int32 layout puts real expert ids in the odd
// slots (P[all zero by chance] = 8^-8192). In-bounds for either dtype.
// ---------------------------------------------------------------------------
__global__ void k_detect(const int* __restrict__ idx32) {
    __shared__ int odd_nonzero;
    if (threadIdx.x == 0) odd_nonzero = 0;
    __syncthreads();
    int local = 0;
    for (int i = threadIdx.x; i < 8192; i += blockDim.x)
        if (idx32[2 * i + 1] != 0) local = 1;
    if (local) odd_nonzero = 1;
    __syncthreads();
    if (threadIdx.x == 0) g_is64 = (odd_nonzero == 0) ? 1 : 0;
}

// ---------------------------------------------------------------------------
// Routing: build per-expert compacted token lists + merged gates
// ---------------------------------------------------------------------------
__global__ void k_zero_counts() {
    if (threadIdx.x < NEXP) g_cnt[threadIdx.x] = 0;
}

__global__ void k_route(const float* __restrict__ p,
                        const void* __restrict__ idxv) {
    int t = blockIdx.x * blockDim.x + threadIdx.x;
    if (t >= TTOK) return;
    int e0, e1;
    if (g_is64) {
        const long long* q = (const long long*)idxv;
        e0 = (int)q[2 * t + 0];
        e1 = (int)q[2 * t + 1];
    } else {
        const int* q = (const int*)idxv;
        e0 = q[2 * t + 0];
        e1 = q[2 * t + 1];
    }
    float p0 = p[2 * t + 0];
    float p1 = p[2 * t + 1];
    bool ok0 = (e0 >= 0 && e0 < NEXP);
    bool ok1 = (e1 >= 0 && e1 < NEXP);
    if (ok0 && ok1 && e0 == e1) {
        int pos = atomicAdd(&g_cnt[e0], 1);
        g_tok[e0 * TTOK + pos]  = t;
        g_gate[e0 * TTOK + pos] = p0 + p1;
    } else {
        if (ok0) {
            int pos = atomicAdd(&g_cnt[e0], 1);
            g_tok[e0 * TTOK + pos]  = t;
            g_gate[e0 * TTOK + pos] = p0;
        }
        if (ok1) {
            int pos = atomicAdd(&g_cnt[e1], 1);
            g_tok[e1 * TTOK + pos]  = t;
            g_gate[e1 * TTOK + pos] = p1;
        }
    }
}

__global__ void k_zero_out(float4* __restrict__ out) {
    size_t i = (size_t)blockIdx.x * blockDim.x + threadIdx.x;
    out[i] = make_float4(0.f, 0.f, 0.f, 0.f);
}

// ---------------------------------------------------------------------------
// GEMM1: Hbuf[i, :] = gelu( x[tok[i], :] @ W1[e] ),  i < cnt[e]
// 128x128 tile, BK=8, 256 threads, 8x8 per thread, FFMA2 core.
// ---------------------------------------------------------------------------
__global__ void __launch_bounds__(256)
k_gemm1(const float* __restrict__ X, const float* __restrict__ W1, int e) {
    const int cnt = g_cnt[e];
    const int m0 = blockIdx.y * 128;
    if (m0 >= cnt) return;
    const int n0 = blockIdx.x * 128;

    __shared__ float As[8][128];
    __shared__ float Bs[8][128];

    const int tid = threadIdx.x;
    const int tx = tid & 15;   // n sub-tile
    const int ty = tid >> 4;   // m sub-tile

    // A load: 2 threads per row, float4 each (8 k-values per row)
    const int arow = tid >> 1;
    const int acol = (tid & 1) * 4;
    int gi = m0 + arow;                       // always within list bounds
    int tok = g_tok[e * TTOK + gi];           // stale beyond cnt: safe, unused
    const float* aptr = X + (size_t)tok * DDIM + acol;

    // B load: 32 threads per k-row, float4 each
    const int brow = tid >> 5;
    const int bcol = (tid & 31) * 4;
    const float* bptr = W1 + (size_t)brow * HDIM + n0 + bcol;

    unsigned long long acc[8][4];
#pragma unroll
    for (int i = 0; i < 8; i++)
#pragma unroll
        for (int j = 0; j < 4; j++) acc[i][j] = 0ull;

    for (int k0 = 0; k0 < DDIM; k0 += 8) {
        float4 av = *(const float4*)(aptr + k0);
        float4 bv = *(const float4*)(bptr + (size_t)k0 * HDIM);
        __syncthreads();
        As[acol + 0][arow] = av.x;
        As[acol + 1][arow] = av.y;
        As[acol + 2][arow] = av.z;
        As[acol + 3][arow] = av.w;
        *(float4*)&Bs[brow][bcol] = bv;
        __syncthreads();
#pragma unroll
        for (int kk = 0; kk < 8; kk++) {
            float4 a0 = *(const float4*)&As[kk][ty * 8];
            float4 a1 = *(const float4*)&As[kk][ty * 8 + 4];
            float a[8] = {a0.x, a0.y, a0.z, a0.w, a1.x, a1.y, a1.z, a1.w};
            const unsigned long long* b2 =
                (const unsigned long long*)&Bs[kk][tx * 8];
            unsigned long long bl[4];
#pragma unroll
            for (int j = 0; j < 4; j++) bl[j] = b2[j];
#pragma unroll
            for (int i = 0; i < 8; i++) {
                unsigned long long ap = pack2(a[i], a[i]);
#pragma unroll
                for (int j = 0; j < 4; j++) ffma2(acc[i][j], ap, bl[j]);
            }
        }
    }

#pragma unroll
    for (int i = 0; i < 8; i++) {
        int row = m0 + ty * 8 + i;
        if (row < cnt) {
            float r[8];
#pragma unroll
            for (int j = 0; j < 4; j++) {
                float lo, hi;
                unpack2(acc[i][j], lo, hi);
                r[2 * j + 0] = gelu_tanh(lo);
                r[2 * j + 1] = gelu_tanh(hi);
            }
            float4* dst = (float4*)&g_hbuf[(size_t)row * HDIM + n0 + tx * 8];
            dst[0] = make_float4(r[0], r[1], r[2], r[3]);
            dst[1] = make_float4(r[4], r[5], r[6], r[7]);
        }
    }
}

// ---------------------------------------------------------------------------
// GEMM2: Y[tok[i], :] += gate[i] * ( Hbuf[i, :] @ W2[e] )
// Scatter += is race-free: one list entry per token per expert, expert
// kernels serialized on the stream.
// ---------------------------------------------------------------------------
__global__ void __launch_bounds__(256)
k_gemm2(const float* __restrict__ W2, int e, float* __restrict__ Y) {
    const int cnt = g_cnt[e];
    const int m0 = blockIdx.y * 128;
    if (m0 >= cnt) return;
    const int n0 = blockIdx.x * 128;

    __shared__ float As[8][128];
    __shared__ float Bs[8][128];

    const int tid = threadIdx.x;
    const int tx = tid & 15;
    const int ty = tid >> 4;

    const int arow = tid >> 1;
    const int acol = (tid & 1) * 4;
    const float* aptr = g_hbuf + (size_t)(m0 + arow) * HDIM + acol;

    const int brow = tid >> 5;
    const int bcol = (tid & 31) * 4;
    const float* bptr = W2 + (size_t)brow * DDIM + n0 + bcol;

    unsigned long long acc[8][4];
#pragma unroll
    for (int i = 0; i < 8; i++)
#pragma unroll
        for (int j = 0; j < 4; j++) acc[i][j] = 0ull;

    for (int k0 = 0; k0 < HDIM; k0 += 8) {
        float4 av = *(const float4*)(aptr + k0);
        float4 bv = *(const float4*)(bptr + (size_t)k0 * DDIM);
        __syncthreads();
        As[acol + 0][arow] = av.x;
        As[acol + 1][arow] = av.y;
        As[acol + 2][arow] = av.z;
        As[acol + 3][arow] = av.w;
        *(float4*)&Bs[brow][bcol] = bv;
        __syncthreads();
#pragma unroll
        for (int kk = 0; kk < 8; kk++) {
            float4 a0 = *(const float4*)&As[kk][ty * 8];
            float4 a1 = *(const float4*)&As[kk][ty * 8 + 4];
            float a[8] = {a0.x, a0.y, a0.z, a0.w, a1.x, a1.y, a1.z, a1.w};
            const unsigned long long* b2 =
                (const unsigned long long*)&Bs[kk][tx * 8];
            unsigned long long bl[4];
#pragma unroll
            for (int j = 0; j < 4; j++) bl[j] = b2[j];
#pragma unroll
            for (int i = 0; i < 8; i++) {
                unsigned long long ap = pack2(a[i], a[i]);
#pragma unroll
                for (int j = 0; j < 4; j++) ffma2(acc[i][j], ap, bl[j]);
            }
        }
    }

#pragma unroll
    for (int i = 0; i < 8; i++) {
        int row = m0 + ty * 8 + i;
        if (row < cnt) {
            int   t    = g_tok[e * TTOK + row];
            float gate = g_gate[e * TTOK + row];
            float r[8];
#pragma unroll
            for (int j = 0; j < 4; j++) {
                float lo, hi;
                unpack2(acc[i][j], lo, hi);
                r[2 * j + 0] = gate * lo;
                r[2 * j + 1] = gate * hi;
            }
            float4* dst = (float4*)(Y + (size_t)t * DDIM + n0 + tx * 8);
            float4 o0 = dst[0];
            float4 o1 = dst[1];
            o0.x += r[0]; o0.y += r[1]; o0.z += r[2]; o0.w += r[3];
            o1.x += r[4]; o1.y += r[5]; o1.z += r[6]; o1.w += r[7];
            dst[0] = o0;
            dst[1] = o1;
        }
    }
}

// ---------------------------------------------------------------------------
// Launch (graph-capturable: kernel launches only, deterministic)
// ---------------------------------------------------------------------------
extern "C" void kernel_launch(void* const* d_in, const int* in_sizes, int n_in,
                              void* d_out, int out_size) {
    const float* x   = (const float*)d_in[0];
    const float* p   = (const float*)d_in[1];
    const void*  idx = d_in[2];              // int64 OR int32 — detected on device
    const float* w1  = (const float*)d_in[3];
    const float* w2  = (const float*)d_in[4];
    float*       y   = (float*)d_out;

    k_detect<<<1, 256>>>((const int*)idx);
    k_zero_counts<<<1, 32>>>();
    k_route<<<TTOK / 256, 256>>>(p, idx);
    k_zero_out<<<(int)(((size_t)TTOK * DDIM / 4) / 256), 256>>>((float4*)y);

    for (int e = 0; e < NEXP; e++) {
        k_gemm1<<<dim3(HDIM / 128, TTOK / 128), 256>>>(
            x, w1 + (size_t)e * DDIM * HDIM, e);
        k_gemm2<<<dim3(DDIM / 128, TTOK / 128), 256>>>(
            w2 + (size_t)e * HDIM * DDIM, e, y);
    }
}

// round 10
// speedup vs baseline: 4.0979x; 4.0979x over previous
#include <cuda_runtime.h>
#include <math.h>
#include <stdint.h>

#define TTOK 8192
#define DDIM 2048
#define HDIM 8192
#define NEXP 8
#define NLIST 16
#define BM 128
#define BN 256
#define BK 32
#define BKP 36            // A smem row stride (floats): banks (4m+k)%32 unique
#define BNP 264           // B smem row stride (floats): banks (8k+n)%32 unique
#define STAGE_F (BM * BKP + BK * BNP)      // 13056 floats per stage
#define SMEM_BYTES (2 * STAGE_F * 4)       // 104448 B

// ---------------- scratch (__device__ globals; no allocs) ------------------
__device__ int   g_is64;
__device__ int   g_cnt[NLIST];
__device__ int   g_off[NLIST];
__device__ int   g_tok[NLIST * TTOK];
__device__ float g_gate[NLIST * TTOK];
__device__ float g_xr[(size_t)TTOK * DDIM];                 // tf32-rounded x
__device__ float g_w1r[(size_t)NEXP * DDIM * HDIM];         // tf32 w1 [e][d][h]
__device__ float g_w2r[(size_t)NEXP * HDIM * DDIM];         // tf32 w2 [e][h][d]
__device__ float g_hbuf[(size_t)(2 * TTOK + BM) * HDIM];    // packed rows, tf32

// ---------------- helpers --------------------------------------------------
__device__ __forceinline__ uint32_t smem_u32(const void* p) {
    uint32_t a;
    asm("{ .reg .u64 t; cvta.to.shared.u64 t, %1; cvt.u32.u64 %0, t; }"
        : "=r"(a) : "l"(p));
    return a;
}
__device__ __forceinline__ uint32_t f2tf32(float x) {
    uint32_t r;
    asm("cvt.rna.tf32.f32 %0, %1;" : "=r"(r) : "f"(x));
    return r;
}
__device__ __forceinline__ void cpa16(uint32_t s, const void* g) {
    asm volatile("cp.async.cg.shared.global [%0], [%1], 16;"
                 :: "r"(s), "l"(g) : "memory");
}
__device__ __forceinline__ void mma8(float* c, const uint32_t* a,
                                     const uint32_t* b) {
    asm volatile(
        "mma.sync.aligned.m16n8k8.row.col.f32.tf32.tf32.f32 "
        "{%0,%1,%2,%3}, {%4,%5,%6,%7}, {%8,%9}, {%0,%1,%2,%3};"
        : "+f"(c[0]), "+f"(c[1]), "+f"(c[2]), "+f"(c[3])
        : "r"(a[0]), "r"(a[1]), "r"(a[2]), "r"(a[3]), "r"(b[0]), "r"(b[1]));
}
__device__ __forceinline__ float gelu_tanh(float v) {
    const float c = 0.7978845608028654f;
    float u = c * (v + 0.044715f * v * v * v);
    return 0.5f * v * (1.0f + tanhf(u));
}

// ---------------- routing --------------------------------------------------
__global__ void k_detect(const int* __restrict__ q) {
    __shared__ int nz;
    if (threadIdx.x == 0) nz = 0;
    __syncthreads();
    int l = 0;
    for (int i = threadIdx.x; i < 8192; i += blockDim.x)
        if (q[2 * i + 1] != 0) l = 1;
    if (l) nz = 1;
    __syncthreads();
    if (threadIdx.x == 0) g_is64 = (nz == 0) ? 1 : 0;
}
__global__ void k_zero_counts() {
    if (threadIdx.x < NLIST) g_cnt[threadIdx.x] = 0;
}
__global__ void k_route(const float* __restrict__ p, const void* __restrict__ iv) {
    int t = blockIdx.x * blockDim.x + threadIdx.x;
    if (t >= TTOK) return;
    int e0, e1;
    if (g_is64) {
        const long long* q = (const long long*)iv;
        e0 = (int)q[2 * t]; e1 = (int)q[2 * t + 1];
    } else {
        const int* q = (const int*)iv;
        e0 = q[2 * t]; e1 = q[2 * t + 1];
    }
    float p0 = p[2 * t], p1 = p[2 * t + 1];
    bool ok0 = (e0 >= 0 && e0 < NEXP), ok1 = (e1 >= 0 && e1 < NEXP);
    if (ok0 && ok1 && e0 == e1) {
        int pos = atomicAdd(&g_cnt[e0], 1);
        g_tok[e0 * TTOK + pos] = t;
        g_gate[e0 * TTOK + pos] = p0 + p1;
    } else {
        if (ok0) {
            int pos = atomicAdd(&g_cnt[e0], 1);
            g_tok[e0 * TTOK + pos] = t;
            g_gate[e0 * TTOK + pos] = p0;
        }
        if (ok1) {
            int L = 8 + e1;
            int pos = atomicAdd(&g_cnt[L], 1);
            g_tok[L * TTOK + pos] = t;
            g_gate[L * TTOK + pos] = p1;
        }
    }
}
__global__ void k_offsets() {
    if (threadIdx.x == 0) {
        int s = 0;
        for (int i = 0; i < NLIST; i++) { g_off[i] = s; s += g_cnt[i]; }
    }
}
__global__ void k_zero_out(float4* __restrict__ o) {
    size_t i = (size_t)blockIdx.x * blockDim.x + threadIdx.x;
    o[i] = make_float4(0.f, 0.f, 0.f, 0.f);
}

// ---------------- tf32 pre-round (sel: 0=w1, 1=w2, 2=x) --------------------
__global__ void k_round(const float4* __restrict__ src, int sel, size_t n4) {
    float4* dst = (sel == 0) ? (float4*)g_w1r
                : (sel == 1) ? (float4*)g_w2r : (float4*)g_xr;
    for (size_t i = (size_t)blockIdx.x * blockDim.x + threadIdx.x; i < n4;
         i += (size_t)gridDim.x * blockDim.x) {
        float4 v = src[i];
        float4 o;
        o.x = __uint_as_float(f2tf32(v.x));
        o.y = __uint_as_float(f2tf32(v.y));
        o.z = __uint_as_float(f2tf32(v.z));
        o.w = __uint_as_float(f2tf32(v.w));
        dst[i] = o;
    }
}

// ---------------- mma.sync tf32 GEMM ---------------------------------------
// P2=false: hbuf[off+i,:] = tf32(gelu(xr[tok,:] @ w1r[e]))   K=DDIM, N=HDIM
// P2=true : Y[tok,:]     += gate * (hbuf[off+i,:] @ w2r[e])  K=HDIM, N=DDIM
template <bool P2>
__global__ void __launch_bounds__(256, 1)
k_gemm(float* __restrict__ yout, int zbase) {
    constexpr int KD = P2 ? HDIM : DDIM;   // reduction length
    constexpr int WN = P2 ? DDIM : HDIM;   // weight row length (n-extent)
    const int L = zbase + blockIdx.z;
    const int cnt = g_cnt[L];
    const int m0 = blockIdx.y * BM;
    if (m0 >= cnt) return;
    const int e = L & 7;
    const int n0 = blockIdx.x * BN;
    const int off = g_off[L];

    extern __shared__ float sm[];
    const uint32_t sm0 = smem_u32(sm);

    const int tid = threadIdx.x;
    // ---- fill thread mapping ----
    const int rb = tid >> 3, cq = tid & 7;           // A: rows rb+32i, 16B col cq
    const int kb = tid >> 6, nc = (tid & 63) * 4;    // B: rows kb+4i, col nc
    const float* aptr[4];
#pragma unroll
    for (int i = 0; i < 4; i++) {
        int m = rb + 32 * i;
        aptr[i] = P2 ? g_hbuf + (size_t)(off + m0 + m) * HDIM + cq * 4
                     : g_xr + (size_t)g_tok[L * TTOK + m0 + m] * DDIM + cq * 4;
    }
    const float* wbase = (P2 ? g_w2r : g_w1r) + (size_t)e * DDIM * HDIM +
                         (size_t)kb * WN + n0 + nc;

    auto issue = [&](int it) {
        const int s = it & 1;
        const uint32_t ab = sm0 + s * (STAGE_F * 4);
        const uint32_t bb = ab + BM * BKP * 4;
        const int k0 = it * BK;
#pragma unroll
        for (int i = 0; i < 4; i++)
            cpa16(ab + (uint32_t)(((rb + 32 * i) * BKP + cq * 4) * 4),
                  aptr[i] + k0);
#pragma unroll
        for (int i = 0; i < 8; i++)
            cpa16(bb + (uint32_t)(((kb + 4 * i) * BNP + nc) * 4),
                  wbase + (size_t)(k0 + 4 * i) * WN);
        asm volatile("cp.async.commit_group;" ::: "memory");
    };

    // ---- compute thread mapping ----
    const int w = tid >> 5, lane = tid & 31;
    const int wm = (w & 1) * 64, wn = (w >> 1) * 64;
    const int gr = lane >> 2, tc = lane & 3;

    float acc[4][8][4];
#pragma unroll
    for (int a = 0; a < 4; a++)
#pragma unroll
        for (int b = 0; b < 8; b++)
#pragma unroll
            for (int c = 0; c < 4; c++) acc[a][b][c] = 0.f;

    constexpr int NIT = KD / BK;
    issue(0);

    for (int it = 0; it < NIT; it++) {
        if (it + 1 < NIT) {
            issue(it + 1);
            asm volatile("cp.async.wait_group 1;" ::: "memory");
        } else {
            asm volatile("cp.async.wait_group 0;" ::: "memory");
        }
        __syncthreads();
        const float* As = sm + (it & 1) * STAGE_F;
        const float* Bs = As + BM * BKP;
#pragma unroll
        for (int ks = 0; ks < 4; ks++) {
            const int kk = ks * 8;
            uint32_t af[4][4], bf[8][2];
#pragma unroll
            for (int mi = 0; mi < 4; mi++) {
                const float* ap = As + (wm + mi * 16 + gr) * BKP + kk + tc;
                af[mi][0] = __float_as_uint(ap[0]);
                af[mi][1] = __float_as_uint(ap[8 * BKP]);
                af[mi][2] = __float_as_uint(ap[4]);
                af[mi][3] = __float_as_uint(ap[8 * BKP + 4]);
            }
#pragma unroll
            for (int ni = 0; ni < 8; ni++) {
                const float* bp = Bs + (kk + tc) * BNP + wn + ni * 8 + gr;
                bf[ni][0] = __float_as_uint(bp[0]);
                bf[ni][1] = __float_as_uint(bp[4 * BNP]);
            }
#pragma unroll
            for (int mi = 0; mi < 4; mi++)
#pragma unroll
                for (int ni = 0; ni < 8; ni++)
                    mma8(acc[mi][ni], af[mi], bf[ni]);
        }
        __syncthreads();
    }

    // ---- epilogue ----
#pragma unroll
    for (int half = 0; half < 2; half++) {
#pragma unroll
        for (int mi = 0; mi < 4; mi++) {
            const int lrow = wm + mi * 16 + gr + half * 8;
            if (m0 + lrow >= cnt) continue;
            if (!P2) {
                float* drow = g_hbuf + (size_t)(off + m0 + lrow) * HDIM + n0;
#pragma unroll
                for (int ni = 0; ni < 8; ni++) {
                    float2 o;
                    o.x = __uint_as_float(
                        f2tf32(gelu_tanh(acc[mi][ni][half * 2 + 0])));
                    o.y = __uint_as_float(
                        f2tf32(gelu_tanh(acc[mi][ni][half * 2 + 1])));
                    *(float2*)(drow + wn + ni * 8 + tc * 2) = o;
                }
            } else {
                const int tok = g_tok[L * TTOK + m0 + lrow];
                const float gate = g_gate[L * TTOK + m0 + lrow];
                float* drow = yout + (size_t)tok * DDIM + n0;
#pragma unroll
                for (int ni = 0; ni < 8; ni++) {
                    float2* dp = (float2*)(drow + wn + ni * 8 + tc * 2);
                    float2 o = *dp;
                    o.x += gate * acc[mi][ni][half * 2 + 0];
                    o.y += gate * acc[mi][ni][half * 2 + 1];
                    *dp = o;
                }
            }
        }
    }
}

// ---------------- launch ---------------------------------------------------
extern "C" void kernel_launch(void* const* d_in, const int* in_sizes, int n_in,
                              void* d_out, int out_size) {
    const float* x = (const float*)d_in[0];
    const float* p = (const float*)d_in[1];
    const void* idx = d_in[2];
    const float* w1 = (const float*)d_in[3];
    const float* w2 = (const float*)d_in[4];
    float* y = (float*)d_out;

    cudaFuncSetAttribute(k_gemm<false>,
                         cudaFuncAttributeMaxDynamicSharedMemorySize, SMEM_BYTES);
    cudaFuncSetAttribute(k_gemm<true>,
                         cudaFuncAttributeMaxDynamicSharedMemorySize, SMEM_BYTES);

    k_detect<<<1, 256>>>((const int*)idx);
    k_zero_counts<<<1, 32>>>();
    k_route<<<TTOK / 256, 256>>>(p, idx);
    k_offsets<<<1, 32>>>();
    k_zero_out<<<(int)(((size_t)TTOK * DDIM / 4) / 256), 256>>>((float4*)y);

    k_round<<<4096, 256>>>((const float4*)w1, 0, (size_t)NEXP * DDIM * HDIM / 4);
    k_round<<<4096, 256>>>((const float4*)w2, 1, (size_t)NEXP * HDIM * DDIM / 4);
    k_round<<<2048, 256>>>((const float4*)x, 2, (size_t)TTOK * DDIM / 4);

    // GEMM1: all 16 lists, disjoint hbuf rows
    k_gemm<false><<<dim3(HDIM / BN, TTOK / BM, NLIST), 256, SMEM_BYTES>>>(
        nullptr, 0);
    // GEMM2: two slot launches (token appears <=1x per slot -> race-free RMW)
    k_gemm<true><<<dim3(DDIM / BN, TTOK / BM, NEXP), 256, SMEM_BYTES>>>(y, 0);
    k_gemm<true><<<dim3(DDIM / BN, TTOK / BM, NEXP), 256, SMEM_BYTES>>>(y, 8);
}